// round 3
// baseline (speedup 1.0000x reference)
#include <cuda_runtime.h>

#define NROWS 8192
#define DDIM  128
#define BM    64
#define BN    64
#define JSPLIT 16
#define NTILES_J (NROWS / BN)                 // 128
#define TILES_PER_SPLIT (NTILES_J / JSPLIT)   // 8
#define MARGINF 1.0f

// ---------------- device scratch (no allocations allowed) ----------------
__device__ float g_vpart[JSPLIT * NROWS];
__device__ float g_V[NROWS];
__device__ float g_hsum[NROWS];
__device__ int   g_cnt[NROWS];

// ---------------- packed f32x2 helpers (Blackwell FFMA2) ----------------
static __device__ __forceinline__ unsigned long long pk2(float lo, float hi) {
    unsigned long long r;
    asm("mov.b64 %0, {%1, %2};" : "=l"(r)
        : "r"(__float_as_uint(lo)), "r"(__float_as_uint(hi)));
    return r;
}
static __device__ __forceinline__ void fma2(unsigned long long& d,
                                            unsigned long long a,
                                            unsigned long long b) {
    asm("fma.rn.f32x2 %0, %1, %2, %0;" : "+l"(d) : "l"(a), "l"(b));
}
static __device__ __forceinline__ void upk2(unsigned long long v, float& lo, float& hi) {
    unsigned int l, h;
    asm("mov.b64 {%0, %1}, %2;" : "=r"(l), "=r"(h) : "l"(v));
    lo = __uint_as_float(l);
    hi = __uint_as_float(h);
}

// Load a [64 rows x 128 k] tile from row-major global into k-major smem
// xs[k*64 + col]. Thread t: col = t&63, k-chunk = (t>>6)*32.
// Global: each thread reads 128B contiguous (full sectors).
// STS: lanes map to consecutive col -> conflict-free.
static __device__ __forceinline__ void load_tile_T(float* xs, const float* __restrict__ src,
                                                   int colBase) {
    int t   = threadIdx.x;
    int col = t & 63;
    int k0  = (t >> 6) << 5;
    const float4* g = reinterpret_cast<const float4*>(src + (size_t)(colBase + col) * DDIM + k0);
    #pragma unroll
    for (int i = 0; i < 8; i++) {
        float4 v = g[i];
        int k = k0 + i * 4;
        xs[(k + 0) * 64 + col] = v.x;
        xs[(k + 1) * 64 + col] = v.y;
        xs[(k + 2) * 64 + col] = v.z;
        xs[(k + 3) * 64 + col] = v.w;
    }
}

// ---------------- pass 1: fused GEMM + exp row-sums (V partials) ----------------
// Block tile: 64 rows x 64 cols, 256 threads, thread tile 4x4 via f32x2 pairs.
extern __shared__ float smem_dyn[];

__global__ void __launch_bounds__(256)
pass1_kernel(const float* __restrict__ a, const float* __restrict__ b,
             const int* __restrict__ labels) {
    float* as   = smem_dyn;                 // [128][64]
    float* bs   = smem_dyn + 128 * 64;      // [128][64]
    float* vred = smem_dyn + 2 * 128 * 64;  // [64][16]
    __shared__ int ls_i[BM];
    __shared__ int ls_j[BN];

    const int rowBase = blockIdx.x * BM;
    const int tid  = threadIdx.x;
    const int warp = tid >> 5, lane = tid & 31;
    const int mg = ((warp >> 1) << 2) + (lane >> 3);  // 0..15
    const int ng = ((warp & 1) << 3) + (lane & 7);    // 0..15
    const int m0 = mg * 4, n0 = ng * 4;

    load_tile_T(as, a, rowBase);
    if (tid < BM) ls_i[tid] = labels[rowBase + tid];
    __syncthreads();

    const int li0 = ls_i[m0 + 0], li1 = ls_i[m0 + 1];
    const int li2 = ls_i[m0 + 2], li3 = ls_i[m0 + 3];
    float vp0 = 0.f, vp1 = 0.f, vp2 = 0.f, vp3 = 0.f;

    const int jt0 = blockIdx.y * TILES_PER_SPLIT;
    for (int t = 0; t < TILES_PER_SPLIT; t++) {
        const int colBase = (jt0 + t) * BN;
        load_tile_T(bs, b, colBase);
        if (tid < BN) ls_j[tid] = labels[colBase + tid];
        __syncthreads();

        unsigned long long acc0 = 0ull, acc1 = 0ull, acc2 = 0ull, acc3 = 0ull;
        unsigned long long acc4 = 0ull, acc5 = 0ull, acc6 = 0ull, acc7 = 0ull;

        #pragma unroll 4
        for (int k = 0; k < DDIM; k++) {
            const float4 av = *reinterpret_cast<const float4*>(&as[k * 64 + m0]);
            const float4 bv = *reinterpret_cast<const float4*>(&bs[k * 64 + n0]);
            const unsigned long long bLo = pk2(bv.x, bv.y);
            const unsigned long long bHi = pk2(bv.z, bv.w);
            unsigned long long aa;
            aa = pk2(av.x, av.x); fma2(acc0, aa, bLo); fma2(acc1, aa, bHi);
            aa = pk2(av.y, av.y); fma2(acc2, aa, bLo); fma2(acc3, aa, bHi);
            aa = pk2(av.z, av.z); fma2(acc4, aa, bLo); fma2(acc5, aa, bHi);
            aa = pk2(av.w, av.w); fma2(acc6, aa, bLo); fma2(acc7, aa, bHi);
        }

        const int lj0 = ls_j[n0 + 0], lj1 = ls_j[n0 + 1];
        const int lj2 = ls_j[n0 + 2], lj3 = ls_j[n0 + 3];
        float s0, s1, s2, s3;

        upk2(acc0, s0, s1); upk2(acc1, s2, s3);
        vp0 += (li0 != lj0 ? __expf(MARGINF + s0) : 0.f)
             + (li0 != lj1 ? __expf(MARGINF + s1) : 0.f)
             + (li0 != lj2 ? __expf(MARGINF + s2) : 0.f)
             + (li0 != lj3 ? __expf(MARGINF + s3) : 0.f);
        upk2(acc2, s0, s1); upk2(acc3, s2, s3);
        vp1 += (li1 != lj0 ? __expf(MARGINF + s0) : 0.f)
             + (li1 != lj1 ? __expf(MARGINF + s1) : 0.f)
             + (li1 != lj2 ? __expf(MARGINF + s2) : 0.f)
             + (li1 != lj3 ? __expf(MARGINF + s3) : 0.f);
        upk2(acc4, s0, s1); upk2(acc5, s2, s3);
        vp2 += (li2 != lj0 ? __expf(MARGINF + s0) : 0.f)
             + (li2 != lj1 ? __expf(MARGINF + s1) : 0.f)
             + (li2 != lj2 ? __expf(MARGINF + s2) : 0.f)
             + (li2 != lj3 ? __expf(MARGINF + s3) : 0.f);
        upk2(acc6, s0, s1); upk2(acc7, s2, s3);
        vp3 += (li3 != lj0 ? __expf(MARGINF + s0) : 0.f)
             + (li3 != lj1 ? __expf(MARGINF + s1) : 0.f)
             + (li3 != lj2 ? __expf(MARGINF + s2) : 0.f)
             + (li3 != lj3 ? __expf(MARGINF + s3) : 0.f);

        __syncthreads();  // before overwriting bs / ls_j
    }

    // reduce V partials across the 16 n-groups
    vred[(m0 + 0) * 16 + ng] = vp0;
    vred[(m0 + 1) * 16 + ng] = vp1;
    vred[(m0 + 2) * 16 + ng] = vp2;
    vred[(m0 + 3) * 16 + ng] = vp3;
    __syncthreads();
    if (tid < BM) {
        float v = 0.f;
        #pragma unroll
        for (int g = 0; g < 16; g++) v += vred[tid * 16 + g];
        g_vpart[blockIdx.y * NROWS + rowBase + tid] = v;  // written exactly once
    }
}

// ---------------- pass 1b: combine V partials (fixed order, deterministic) ----------------
__global__ void combine_kernel() {
    int i = blockIdx.x * blockDim.x + threadIdx.x;
    if (i < NROWS) {
        float v = 0.f;
        #pragma unroll
        for (int s = 0; s < JSPLIT; s++) v += g_vpart[s * NROWS + i];
        g_V[i] = v;
    }
}

// ---------------- pass 2: positive pairs (sparse, ~65k dots) ----------------
__global__ void __launch_bounds__(256)
pass2_kernel(const float* __restrict__ a, const float* __restrict__ b,
             const int* __restrict__ labels) {
    const int warp = threadIdx.x >> 5, lane = threadIdx.x & 31;
    const int i = blockIdx.x * 8 + warp;

    const float4 af = *reinterpret_cast<const float4*>(&a[(size_t)i * DDIM + lane * 4]);
    const int li = labels[i];
    const float Vi = g_V[i];

    float hs = 0.f;
    int cnt = 0;

    for (int jb = 0; jb < NROWS; jb += 32) {
        const int j = jb + lane;
        const int lj = labels[j];
        const bool match = (lj == li) && (j != i);
        unsigned mask = __ballot_sync(0xffffffffu, match);
        while (mask) {
            const int jl = __ffs(mask) - 1;
            mask &= mask - 1;
            const int jj = jb + jl;
            const float4 bf = *reinterpret_cast<const float4*>(&b[(size_t)jj * DDIM + lane * 4]);
            float p = af.x * bf.x + af.y * bf.y + af.z * bf.z + af.w * bf.w;
            #pragma unroll
            for (int off = 16; off; off >>= 1) p += __shfl_xor_sync(0xffffffffu, p, off);
            if (lane == jl) {
                const float h = fmaxf(logf(Vi + g_V[jj]) - p, 0.f);
                hs += h * h;
                cnt++;
            }
        }
    }
    #pragma unroll
    for (int off = 16; off; off >>= 1) {
        hs  += __shfl_xor_sync(0xffffffffu, hs, off);
        cnt += __shfl_xor_sync(0xffffffffu, cnt, off);
    }
    if (lane == 0) {
        g_hsum[i] = hs;
        g_cnt[i]  = cnt;
    }
}

// ---------------- pass 3: final deterministic reduction ----------------
__global__ void finalize_kernel(float* __restrict__ out) {
    __shared__ float sh[256];
    __shared__ int   sc[256];
    const int t = threadIdx.x;
    float s = 0.f;
    int   c = 0;
    for (int i = t; i < NROWS; i += 256) {
        s += g_hsum[i];
        c += g_cnt[i];
    }
    sh[t] = s;
    sc[t] = c;
    __syncthreads();
    for (int o = 128; o; o >>= 1) {
        if (t < o) { sh[t] += sh[t + o]; sc[t] += sc[t + o]; }
        __syncthreads();
    }
    if (t == 0) out[0] = sh[0] / (2.0f * (float)sc[0]);
}

// ---------------- launch ----------------
extern "C" void kernel_launch(void* const* d_in, const int* in_sizes, int n_in,
                              void* d_out, int out_size) {
    const float* a      = (const float*)d_in[0];
    const float* b      = (const float*)d_in[1];
    const int*   labels = (const int*)d_in[2];
    float*       out    = (float*)d_out;

    const int smemBytes = (2 * 128 * 64 + 64 * 16) * (int)sizeof(float);  // 69632
    cudaFuncSetAttribute(pass1_kernel, cudaFuncAttributeMaxDynamicSharedMemorySize, smemBytes);

    dim3 g1(NROWS / BM, JSPLIT);   // (128, 16) = 2048 CTAs
    pass1_kernel<<<g1, 256, smemBytes>>>(a, b, labels);
    combine_kernel<<<NROWS / 256, 256>>>();
    pass2_kernel<<<NROWS / 8, 256>>>(a, b, labels);
    finalize_kernel<<<1, 256>>>(out);
}

// round 5
// speedup vs baseline: 4.0854x; 4.0854x over previous
#include <cuda_runtime.h>
#include <cuda_fp16.h>
#include <cstdint>

#define NROWS   8192
#define DDIM    128
#define JSPLIT  16
#define TILES_PER_CTA 4          // 64 j-tiles / 16 splits
#define MARGINF 1.0f

// smem tile: 128 rows x 128 fp16, padded row stride 136 fp16 = 272 B
#define TSTRIDE 272
#define TILE_BYTES (128 * TSTRIDE)   // 34816

// ---------------- device scratch (no allocations allowed) ----------------
__device__ __half g_af[NROWS * DDIM];
__device__ __half g_bf[NROWS * DDIM];
__device__ float g_vpart[JSPLIT * NROWS];
__device__ float g_V[NROWS];
__device__ float g_hsum[NROWS];
__device__ int   g_cnt[NROWS];

// ---------------- helpers ----------------
static __device__ __forceinline__ uint32_t smem_u32(const void* p) {
    uint32_t a;
    asm("{ .reg .u64 t; cvta.to.shared.u64 t, %1; cvt.u32.u64 %0, t; }" : "=r"(a) : "l"(p));
    return a;
}
static __device__ __forceinline__ void cp16(uint32_t dst, const void* src) {
    asm volatile("cp.async.cg.shared.global [%0], [%1], 16;" :: "r"(dst), "l"(src));
}
#define CP_COMMIT()  asm volatile("cp.async.commit_group;" ::: "memory")
#define CP_WAIT0()   asm volatile("cp.async.wait_group 0;" ::: "memory")

static __device__ __forceinline__ void ldsm4(uint32_t& r0, uint32_t& r1,
                                             uint32_t& r2, uint32_t& r3, uint32_t addr) {
    asm volatile("ldmatrix.sync.aligned.m8n8.x4.shared.b16 {%0,%1,%2,%3}, [%4];"
                 : "=r"(r0), "=r"(r1), "=r"(r2), "=r"(r3) : "r"(addr));
}
static __device__ __forceinline__ void mma16816(float& d0, float& d1, float& d2, float& d3,
        uint32_t a0, uint32_t a1, uint32_t a2, uint32_t a3, uint32_t b0, uint32_t b1) {
    asm volatile(
        "mma.sync.aligned.m16n8k16.row.col.f32.f16.f16.f32 "
        "{%0,%1,%2,%3}, {%4,%5,%6,%7}, {%8,%9}, {%0,%1,%2,%3};"
        : "+f"(d0), "+f"(d1), "+f"(d2), "+f"(d3)
        : "r"(a0), "r"(a1), "r"(a2), "r"(a3), "r"(b0), "r"(b1));
}

// ---------------- conversion: fp32 -> fp16 (inputs are unit-norm rows) ----------------
__global__ void __launch_bounds__(256)
convert_kernel(const float* __restrict__ a, const float* __restrict__ b) {
    int i = (blockIdx.x * 256 + threadIdx.x) * 4;
    float4 va = *reinterpret_cast<const float4*>(a + i);
    float4 vb = *reinterpret_cast<const float4*>(b + i);
    __half2* pa = reinterpret_cast<__half2*>(g_af + i);
    __half2* pb = reinterpret_cast<__half2*>(g_bf + i);
    pa[0] = __floats2half2_rn(va.x, va.y);
    pa[1] = __floats2half2_rn(va.z, va.w);
    pb[0] = __floats2half2_rn(vb.x, vb.y);
    pb[1] = __floats2half2_rn(vb.z, vb.w);
}

// issue cp.async for a 128x128 fp16 tile (8 x 16B per thread)
static __device__ __forceinline__ void tile_cp_async(uint32_t dst_base,
        const __half* __restrict__ src, int rowBase) {
    const int t = threadIdx.x;
    #pragma unroll
    for (int it = 0; it < 8; it++) {
        int g = t + it * 256;        // 0..2047
        int r = g >> 4;
        int c = g & 15;              // 16B chunk within row
        cp16(dst_base + (uint32_t)(r * TSTRIDE + c * 16),
             src + (size_t)(rowBase + r) * DDIM + c * 8);
    }
}

// ---------------- pass 1: HMMA GEMM + fused masked exp row-sums ----------------
extern __shared__ char smem_raw[];

__global__ void __launch_bounds__(256, 1)
pass1_mma(const int* __restrict__ labels) {
    char* As = smem_raw;
    char* Bs0 = smem_raw + TILE_BYTES;
    char* Bs1 = smem_raw + 2 * TILE_BYTES;

    __shared__ int   ls_i[128];
    __shared__ int   ls_j[2][128];
    __shared__ float vred[128][2];

    const int tid  = threadIdx.x;
    const int wid  = tid >> 5;
    const int lane = tid & 31;
    const int wm   = wid >> 1;          // 0..3  (rows: wm*32)
    const int wn   = wid & 1;           // 0..1  (cols: wn*64)
    const int rowBase = blockIdx.x * 128;
    const int jt0     = blockIdx.y * TILES_PER_CTA;

    const uint32_t asu = smem_u32(As);
    const uint32_t bsu[2] = { smem_u32(Bs0), smem_u32(Bs1) };

    // prologue: A tile + B tile 0
    tile_cp_async(asu, g_af, rowBase);
    tile_cp_async(bsu[0], g_bf, jt0 * 128);
    CP_COMMIT();
    if (tid < 128) {
        ls_i[tid]    = labels[rowBase + tid];
        ls_j[0][tid] = labels[jt0 * 128 + tid];
    }
    CP_WAIT0();
    __syncthreads();

    // per-lane ldmatrix base addresses
    // A (m16k16 row-major): lanes 0-15 -> row m=lane, k-lo; 16-31 -> m=lane-16, k-hi(+16B)
    const uint32_t aoff = (uint32_t)((wm * 32 + (lane & 15)) * TSTRIDE + ((lane >> 4) << 4));
    // B (k16n8 from n-major rows): lanes 0-7:(n,klo) 8-15:(n,khi) 16-23:(n+8,klo) 24-31:(n+8,khi)
    const uint32_t boff = (uint32_t)((wn * 64 + (lane & 7) + ((lane >> 4) << 3)) * TSTRIDE
                                     + (((lane >> 3) & 1) << 4));

    // row labels owned by this thread (4 rows)
    const int r0 = wm * 32 + (lane >> 2);
    const int li00 = ls_i[r0];       // mf0 row
    const int li01 = ls_i[r0 + 8];   // mf0 row+8
    const int li10 = ls_i[r0 + 16];  // mf1 row
    const int li11 = ls_i[r0 + 24];  // mf1 row+8
    float vr00 = 0.f, vr01 = 0.f, vr10 = 0.f, vr11 = 0.f;

    for (int t = 0; t < TILES_PER_CTA; t++) {
        const int cb = t & 1, nb = (t + 1) & 1;
        if (t + 1 < TILES_PER_CTA) {
            tile_cp_async(bsu[nb], g_bf, (jt0 + t + 1) * 128);
            CP_COMMIT();
            if (tid < 128) ls_j[nb][tid] = labels[(jt0 + t + 1) * 128 + tid];
        }

        float acc[2][8][4];
        #pragma unroll
        for (int mf = 0; mf < 2; mf++)
            #pragma unroll
            for (int nf = 0; nf < 8; nf++)
                #pragma unroll
                for (int c = 0; c < 4; c++) acc[mf][nf][c] = 0.f;

        const uint32_t bbase = bsu[cb] + boff;
        #pragma unroll
        for (int ks = 0; ks < 8; ks++) {
            const uint32_t kb = (uint32_t)(ks * 32);
            uint32_t aF[2][4];
            #pragma unroll
            for (int mf = 0; mf < 2; mf++)
                ldsm4(aF[mf][0], aF[mf][1], aF[mf][2], aF[mf][3],
                      asu + aoff + (uint32_t)(mf * 16 * TSTRIDE) + kb);
            uint32_t bF[8][2];
            #pragma unroll
            for (int np = 0; np < 4; np++) {
                uint32_t q0, q1, q2, q3;
                ldsm4(q0, q1, q2, q3, bbase + (uint32_t)(np * 16 * TSTRIDE) + kb);
                bF[np * 2 + 0][0] = q0; bF[np * 2 + 0][1] = q1;
                bF[np * 2 + 1][0] = q2; bF[np * 2 + 1][1] = q3;
            }
            #pragma unroll
            for (int mf = 0; mf < 2; mf++)
                #pragma unroll
                for (int nf = 0; nf < 8; nf++)
                    mma16816(acc[mf][nf][0], acc[mf][nf][1], acc[mf][nf][2], acc[mf][nf][3],
                             aF[mf][0], aF[mf][1], aF[mf][2], aF[mf][3],
                             bF[nf][0], bF[nf][1]);
        }

        // epilogue: masked exp row-sums (cols this thread owns: nf*8 + (lane&3)*2 {,+1})
        #pragma unroll
        for (int nf = 0; nf < 8; nf++) {
            const int col = wn * 64 + nf * 8 + ((lane & 3) << 1);
            const int2 lj = *reinterpret_cast<const int2*>(&ls_j[cb][col]);
            vr00 += (li00 != lj.x ? __expf(MARGINF + acc[0][nf][0]) : 0.f)
                  + (li00 != lj.y ? __expf(MARGINF + acc[0][nf][1]) : 0.f);
            vr01 += (li01 != lj.x ? __expf(MARGINF + acc[0][nf][2]) : 0.f)
                  + (li01 != lj.y ? __expf(MARGINF + acc[0][nf][3]) : 0.f);
            vr10 += (li10 != lj.x ? __expf(MARGINF + acc[1][nf][0]) : 0.f)
                  + (li10 != lj.y ? __expf(MARGINF + acc[1][nf][1]) : 0.f);
            vr11 += (li11 != lj.x ? __expf(MARGINF + acc[1][nf][2]) : 0.f)
                  + (li11 != lj.y ? __expf(MARGINF + acc[1][nf][3]) : 0.f);
        }

        if (t + 1 < TILES_PER_CTA) CP_WAIT0();
        __syncthreads();
    }

    // deterministic reduction: quad shuffle -> vred -> 2-way sum
    #pragma unroll
    for (int off = 1; off <= 2; off <<= 1) {
        vr00 += __shfl_xor_sync(0xffffffffu, vr00, off);
        vr01 += __shfl_xor_sync(0xffffffffu, vr01, off);
        vr10 += __shfl_xor_sync(0xffffffffu, vr10, off);
        vr11 += __shfl_xor_sync(0xffffffffu, vr11, off);
    }
    if ((lane & 3) == 0) {
        vred[r0     ][wn] = vr00;
        vred[r0 +  8][wn] = vr01;
        vred[r0 + 16][wn] = vr10;
        vred[r0 + 24][wn] = vr11;
    }
    __syncthreads();
    if (tid < 128)
        g_vpart[blockIdx.y * NROWS + rowBase + tid] = vred[tid][0] + vred[tid][1];
}

// ---------------- pass 1b: combine V partials (fixed order, deterministic) ----------------
__global__ void combine_kernel() {
    int i = blockIdx.x * blockDim.x + threadIdx.x;
    if (i < NROWS) {
        float v = 0.f;
        #pragma unroll
        for (int s = 0; s < JSPLIT; s++) v += g_vpart[s * NROWS + i];
        g_V[i] = v;
    }
}

// ---------------- pass 2: positive pairs (sparse, exact fp32 dots) ----------------
__global__ void __launch_bounds__(256)
pass2_kernel(const float* __restrict__ a, const float* __restrict__ b,
             const int* __restrict__ labels) {
    const int warp = threadIdx.x >> 5, lane = threadIdx.x & 31;
    const int i = blockIdx.x * 8 + warp;

    const float4 af = *reinterpret_cast<const float4*>(&a[(size_t)i * DDIM + lane * 4]);
    const int li = labels[i];
    const float Vi = g_V[i];

    float hs = 0.f;
    int cnt = 0;

    for (int jb = 0; jb < NROWS; jb += 32) {
        const int j = jb + lane;
        const int lj = labels[j];
        const bool match = (lj == li) && (j != i);
        unsigned mask = __ballot_sync(0xffffffffu, match);
        while (mask) {
            const int jl = __ffs(mask) - 1;
            mask &= mask - 1;
            const int jj = jb + jl;
            const float4 bf = *reinterpret_cast<const float4*>(&b[(size_t)jj * DDIM + lane * 4]);
            float p = af.x * bf.x + af.y * bf.y + af.z * bf.z + af.w * bf.w;
            #pragma unroll
            for (int off = 16; off; off >>= 1) p += __shfl_xor_sync(0xffffffffu, p, off);
            if (lane == jl) {
                const float h = fmaxf(logf(Vi + g_V[jj]) - p, 0.f);
                hs += h * h;
                cnt++;
            }
        }
    }
    #pragma unroll
    for (int off = 16; off; off >>= 1) {
        hs  += __shfl_xor_sync(0xffffffffu, hs, off);
        cnt += __shfl_xor_sync(0xffffffffu, cnt, off);
    }
    if (lane == 0) {
        g_hsum[i] = hs;
        g_cnt[i]  = cnt;
    }
}

// ---------------- pass 3: final deterministic reduction ----------------
__global__ void finalize_kernel(float* __restrict__ out) {
    __shared__ float sh[256];
    __shared__ int   sc[256];
    const int t = threadIdx.x;
    float s = 0.f;
    int   c = 0;
    for (int i = t; i < NROWS / 4; i += 256) {
        float4 v = reinterpret_cast<const float4*>(g_hsum)[i];
        s += (v.x + v.y) + (v.z + v.w);
        int4 cc = reinterpret_cast<const int4*>(g_cnt)[i];
        c += cc.x + cc.y + cc.z + cc.w;
    }
    sh[t] = s;
    sc[t] = c;
    __syncthreads();
    for (int o = 128; o; o >>= 1) {
        if (t < o) { sh[t] += sh[t + o]; sc[t] += sc[t + o]; }
        __syncthreads();
    }
    if (t == 0) out[0] = sh[0] / (2.0f * (float)sc[0]);
}

// ---------------- launch ----------------
extern "C" void kernel_launch(void* const* d_in, const int* in_sizes, int n_in,
                              void* d_out, int out_size) {
    const float* a      = (const float*)d_in[0];
    const float* b      = (const float*)d_in[1];
    const int*   labels = (const int*)d_in[2];
    float*       out    = (float*)d_out;

    const int smemBytes = 3 * TILE_BYTES;   // 104448: A + double-buffered B
    cudaFuncSetAttribute(pass1_mma, cudaFuncAttributeMaxDynamicSharedMemorySize, smemBytes);

    convert_kernel<<<NROWS * DDIM / 1024, 256>>>(a, b);
    dim3 g1(NROWS / 128, JSPLIT);           // (64, 16) = 1024 CTAs
    pass1_mma<<<g1, 256, smemBytes>>>(labels);
    combine_kernel<<<NROWS / 256, 256>>>();
    pass2_kernel<<<NROWS / 8, 256>>>(a, b, labels);
    finalize_kernel<<<1, 256>>>(out);
}